// round 4
// baseline (speedup 1.0000x reference)
#include <cuda_runtime.h>
#include <cuda_fp16.h>

// ---------------------------------------------------------------------------
// 3-layer GCN. edge_index int32. CSR gather, H stored fp16 (halves L2 bytes).
// GEMM: 8x4 register tile, warp-uniform X broadcast, fp32 accum.
// ---------------------------------------------------------------------------

#define NN 50000
#define EE 640000

__device__ __half g_h[NN * 128];     // per-layer linear output (fp16)
__device__ float  g_agg1[NN * 128];
__device__ float  g_agg2[NN * 128];
__device__ float  g_dis[NN];         // (deg)^-1/2
__device__ float  g_dinv[NN];        // (deg)^-1
__device__ int    g_degi[NN];        // in-degree (excl self)
__device__ int    g_start[NN + 1];   // CSR offsets
__device__ int    g_cursor[NN];
__device__ int2   g_adj[EE];         // (src, coef bits)

// ---------------------------------------------------------------------------
__global__ void k_count(const int* __restrict__ dst, int* degi, int e) {
    int i = blockIdx.x * blockDim.x + threadIdx.x;
    if (i < e) atomicAdd(&degi[dst[i]], 1);
}

__global__ void __launch_bounds__(1024) k_scan(
    const int* __restrict__ degi, int* start, int* cursor,
    float* dis, float* dinv, int n)
{
    const int T = 1024;
    int tid = threadIdx.x;
    int chunk = (n + T - 1) / T;
    int lo = tid * chunk;
    int hi = min(lo + chunk, n);

    int sum = 0;
    for (int i = lo; i < hi; i++) sum += degi[i];

    __shared__ int ssum[T];
    ssum[tid] = sum;
    __syncthreads();
    for (int off = 1; off < T; off *= 2) {
        int v = (tid >= off) ? ssum[tid - off] : 0;
        __syncthreads();
        ssum[tid] += v;
        __syncthreads();
    }
    int run = (tid == 0) ? 0 : ssum[tid - 1];
    for (int i = lo; i < hi; i++) {
        int d = degi[i];
        start[i]  = run;
        cursor[i] = run;
        float df = (float)(d + 1);
        dis[i]  = rsqrtf(df);
        dinv[i] = 1.0f / df;
        run += d;
    }
    if (tid == T - 1) start[n] = ssum[T - 1];
}

__global__ void k_fill(const int* __restrict__ src, const int* __restrict__ dst,
                       const float* __restrict__ dis, int* cursor, int2* adj, int e)
{
    int i = blockIdx.x * blockDim.x + threadIdx.x;
    if (i >= e) return;
    int s = src[i], d = dst[i];
    int pos = atomicAdd(&cursor[d], 1);
    adj[pos] = make_int2(s, __float_as_int(dis[s] * dis[d]));
}

// ---------------------------------------------------------------------------
// GEMM: H[nrows,C] = act(X)[nrows,128] @ W[128,C]   (H stored as fp16)
// AGG = H*dinv + bias (fp32).  8 rows x 4 cols per thread.
// ---------------------------------------------------------------------------
template <int C, bool RELU>
__global__ void __launch_bounds__(256, 3) k_gemm(
    const float* __restrict__ X, const float* __restrict__ W,
    const float* __restrict__ bias, const float* __restrict__ dinv,
    __half* __restrict__ H, float* __restrict__ AGG, int nrows)
{
    constexpr int CG = C / 4;        // col groups (32 or 16)
    constexpr int RG = 256 / CG;     // row groups (8 or 16)
    constexpr int MT = RG * 8;       // rows per block (64 or 128)
    constexpr int KT = 16;

    __shared__ __align__(16) float Xs[KT][MT + 4];   // k-major
    __shared__ __align__(16) float Ws[KT][C];

    const int t  = threadIdx.x;
    const int cx = t % CG;
    const int ry = t / CG;
    const int m0 = blockIdx.x * MT;

    float acc[8][4] = {};

    for (int k0 = 0; k0 < 128; k0 += KT) {
        // X tile -> k-major smem (MT*4 float4s)
        #pragma unroll
        for (int l = 0; l < MT / 64; l++) {
            int idx = t + l * 256;
            int row = idx / 4;
            int j   = idx % 4;
            float4 v = make_float4(0.f, 0.f, 0.f, 0.f);
            if (m0 + row < nrows)
                v = *(const float4*)&X[(m0 + row) * 128 + k0 + j * 4];
            if (RELU) {
                v.x = fmaxf(v.x, 0.f); v.y = fmaxf(v.y, 0.f);
                v.z = fmaxf(v.z, 0.f); v.w = fmaxf(v.w, 0.f);
            }
            Xs[j * 4 + 0][row] = v.x;
            Xs[j * 4 + 1][row] = v.y;
            Xs[j * 4 + 2][row] = v.z;
            Xs[j * 4 + 3][row] = v.w;
        }
        // W tile (KT*C/4 float4s)
        #pragma unroll
        for (int l = 0; l < (KT * C / 4) / 256; l++) {
            int idx = t + l * 256;
            int k   = idx / (C / 4);
            int cq  = idx % (C / 4);
            *(float4*)&Ws[k][cq * 4] = *(const float4*)&W[(k0 + k) * C + cq * 4];
        }
        __syncthreads();

        #pragma unroll
        for (int k = 0; k < KT; k++) {
            float xr[8], wr[4];
            *(float4*)&xr[0] = *(const float4*)&Xs[k][ry * 8];
            *(float4*)&xr[4] = *(const float4*)&Xs[k][ry * 8 + 4];
            *(float4*)&wr[0] = *(const float4*)&Ws[k][cx * 4];
            #pragma unroll
            for (int i = 0; i < 8; i++)
                #pragma unroll
                for (int j = 0; j < 4; j++)
                    acc[i][j] = fmaf(xr[i], wr[j], acc[i][j]);
        }
        __syncthreads();
    }

    float4 bv = *(const float4*)&bias[cx * 4];
    #pragma unroll
    for (int i = 0; i < 8; i++) {
        int row = m0 + ry * 8 + i;
        if (row < nrows) {
            float di = dinv[row];
            // H as fp16 (4 halves = 8B store)
            __half2 h0 = __floats2half2_rn(acc[i][0], acc[i][1]);
            __half2 h1 = __floats2half2_rn(acc[i][2], acc[i][3]);
            *(__half2*)&H[row * C + cx * 4 + 0] = h0;
            *(__half2*)&H[row * C + cx * 4 + 2] = h1;
            float4 av = make_float4(fmaf(acc[i][0], di, bv.x),
                                    fmaf(acc[i][1], di, bv.y),
                                    fmaf(acc[i][2], di, bv.z),
                                    fmaf(acc[i][3], di, bv.w));
            *(float4*)&AGG[row * C + cx * 4] = av;
        }
    }
}

// ---------------------------------------------------------------------------
// CSR gather: AGG[d] += sum_e H[src_e] * coef_e.  One warp per node.
// Lane handles C/32 halves. adj entries batch-loaded and shfl-distributed.
// ---------------------------------------------------------------------------
template <int C>
__global__ void __launch_bounds__(256) k_gather(
    const int* __restrict__ start, const int2* __restrict__ adj,
    const __half* __restrict__ H, float* __restrict__ AGG, int n)
{
    int warp = (blockIdx.x * blockDim.x + threadIdx.x) >> 5;
    int lane = threadIdx.x & 31;
    if (warp >= n) return;
    int node = warp;

    int s0 = start[node];
    int s1 = start[node + 1];

    if (C == 128) {
        float4 acc = *(const float4*)&AGG[node * 128 + lane * 4];
        for (int base = s0; base < s1; base += 32) {
            int nb = min(32, s1 - base);
            long long areg = 0;
            if (base + lane < s1)
                areg = *(const long long*)&adj[base + lane];
            #pragma unroll 4
            for (int j = 0; j < nb; j++) {
                long long a = __shfl_sync(0xffffffffu, areg, j);
                int   sidx = (int)(unsigned int)(a & 0xffffffffll);
                float coef = __int_as_float((int)(a >> 32));
                uint2 hv = *(const uint2*)&H[sidx * 128 + lane * 4];
                float2 f0 = __half22float2(*(const __half2*)&hv.x);
                float2 f1 = __half22float2(*(const __half2*)&hv.y);
                acc.x = fmaf(f0.x, coef, acc.x);
                acc.y = fmaf(f0.y, coef, acc.y);
                acc.z = fmaf(f1.x, coef, acc.z);
                acc.w = fmaf(f1.y, coef, acc.w);
            }
        }
        *(float4*)&AGG[node * 128 + lane * 4] = acc;
    } else {
        float2 acc = *(const float2*)&AGG[node * 64 + lane * 2];
        for (int base = s0; base < s1; base += 32) {
            int nb = min(32, s1 - base);
            long long areg = 0;
            if (base + lane < s1)
                areg = *(const long long*)&adj[base + lane];
            #pragma unroll 4
            for (int j = 0; j < nb; j++) {
                long long a = __shfl_sync(0xffffffffu, areg, j);
                int   sidx = (int)(unsigned int)(a & 0xffffffffll);
                float coef = __int_as_float((int)(a >> 32));
                unsigned int hv = *(const unsigned int*)&H[sidx * 64 + lane * 2];
                float2 f0 = __half22float2(*(const __half2*)&hv);
                acc.x = fmaf(f0.x, coef, acc.x);
                acc.y = fmaf(f0.y, coef, acc.y);
            }
        }
        *(float2*)&AGG[node * 64 + lane * 2] = acc;
    }
}

// ---------------------------------------------------------------------------
extern "C" void kernel_launch(void* const* d_in, const int* in_sizes, int n_in,
                              void* d_out, int out_size)
{
    const float* x  = (const float*)d_in[0];
    const int*   ei = (const int*)d_in[1];
    const float* W1 = (const float*)d_in[2];
    const float* b1 = (const float*)d_in[3];
    const float* W2 = (const float*)d_in[4];
    const float* b2 = (const float*)d_in[5];
    const float* W3 = (const float*)d_in[6];
    const float* b3 = (const float*)d_in[7];
    float* out = (float*)d_out;

    const int E = in_sizes[1] / 2;
    const int N = in_sizes[0] / 128;
    const int* src = ei;
    const int* dst = ei + E;

    __half* ph;
    float *pa1, *pa2, *pdis, *pdinv;
    int *pdegi, *pstart, *pcursor;
    int2 *padj;
    cudaGetSymbolAddress((void**)&ph,      g_h);
    cudaGetSymbolAddress((void**)&pa1,     g_agg1);
    cudaGetSymbolAddress((void**)&pa2,     g_agg2);
    cudaGetSymbolAddress((void**)&pdis,    g_dis);
    cudaGetSymbolAddress((void**)&pdinv,   g_dinv);
    cudaGetSymbolAddress((void**)&pdegi,   g_degi);
    cudaGetSymbolAddress((void**)&pstart,  g_start);
    cudaGetSymbolAddress((void**)&pcursor, g_cursor);
    cudaGetSymbolAddress((void**)&padj,    g_adj);

    // CSR build
    cudaMemsetAsync(pdegi, 0, N * sizeof(int));
    k_count<<<(E + 255) / 256, 256>>>(dst, pdegi, E);
    k_scan<<<1, 1024>>>(pdegi, pstart, pcursor, pdis, pdinv, N);
    k_fill<<<(E + 255) / 256, 256>>>(src, dst, pdis, pcursor, padj, E);

    const int g128 = (N + 63) / 64;     // MT=64
    const int g64  = (N + 127) / 128;   // MT=128
    const int gatb = (N * 32 + 255) / 256;

    // layer 1
    k_gemm<128, false><<<g128, 256>>>(x, W1, b1, pdinv, ph, pa1, N);
    k_gather<128><<<gatb, 256>>>(pstart, padj, ph, pa1, N);
    // layer 2
    k_gemm<128, true><<<g128, 256>>>(pa1, W2, b2, pdinv, ph, pa2, N);
    k_gather<128><<<gatb, 256>>>(pstart, padj, ph, pa2, N);
    // layer 3 (C=64)
    k_gemm<64, true><<<g64, 256>>>(pa2, W3, b3, pdinv, ph, out, N);
    k_gather<64><<<gatb, 256>>>(pstart, padj, ph, out, N);
}

// round 6
// speedup vs baseline: 1.9322x; 1.9322x over previous
#include <cuda_runtime.h>
#include <cuda_fp16.h>
#include <cstdint>

// ---------------------------------------------------------------------------
// 3-layer GCN. HMMA (mma.sync m16n8k16 f16->f32) GEMM + CSR fp16 gather.
// ---------------------------------------------------------------------------

#define NN 50000
#define EE 640000

__device__ __half g_h[NN * 128];     // linear output, fp16
__device__ float  g_agg1[NN * 128];
__device__ float  g_agg2[NN * 128];
__device__ float  g_dis[NN];
__device__ float  g_dinv[NN];
__device__ int    g_degi[NN];
__device__ int    g_start[NN + 1];
__device__ int    g_cursor[NN];
__device__ int2   g_adj[EE];
__device__ __half g_wt1[128 * 128];  // W^T fp16 [C][K]
__device__ __half g_wt2[128 * 128];
__device__ __half g_wt3[64 * 128];

__device__ __forceinline__ uint32_t smem_u32(const void* p) {
    uint32_t a;
    asm("{ .reg .u64 t; cvta.to.shared.u64 t, %1; cvt.u32.u64 %0, t; }"
        : "=r"(a) : "l"(p));
    return a;
}
__device__ __forceinline__ void ldm4(uint32_t* r, uint32_t addr) {
    asm volatile("ldmatrix.sync.aligned.m8n8.x4.shared.b16 {%0,%1,%2,%3}, [%4];"
                 : "=r"(r[0]), "=r"(r[1]), "=r"(r[2]), "=r"(r[3]) : "r"(addr));
}
__device__ __forceinline__ void mma16816(float* d, const uint32_t* a,
                                         uint32_t b0, uint32_t b1) {
    asm volatile(
        "mma.sync.aligned.m16n8k16.row.col.f32.f16.f16.f32 "
        "{%0,%1,%2,%3}, {%4,%5,%6,%7}, {%8,%9}, {%0,%1,%2,%3};"
        : "+f"(d[0]), "+f"(d[1]), "+f"(d[2]), "+f"(d[3])
        : "r"(a[0]), "r"(a[1]), "r"(a[2]), "r"(a[3]), "r"(b0), "r"(b1));
}

// ---------------------------------------------------------------------------
// degree + CSR build
// ---------------------------------------------------------------------------
__global__ void k_count(const int* __restrict__ dst, int* degi, int e) {
    int i = blockIdx.x * blockDim.x + threadIdx.x;
    if (i < e) atomicAdd(&degi[dst[i]], 1);
}
__global__ void __launch_bounds__(1024) k_scan(
    const int* __restrict__ degi, int* start, int* cursor,
    float* dis, float* dinv, int n)
{
    const int T = 1024;
    int tid = threadIdx.x;
    int chunk = (n + T - 1) / T;
    int lo = tid * chunk, hi = min(lo + chunk, n);
    int sum = 0;
    for (int i = lo; i < hi; i++) sum += degi[i];
    __shared__ int ssum[T];
    ssum[tid] = sum;
    __syncthreads();
    for (int off = 1; off < T; off *= 2) {
        int v = (tid >= off) ? ssum[tid - off] : 0;
        __syncthreads();
        ssum[tid] += v;
        __syncthreads();
    }
    int run = (tid == 0) ? 0 : ssum[tid - 1];
    for (int i = lo; i < hi; i++) {
        int d = degi[i];
        start[i] = run; cursor[i] = run;
        float df = (float)(d + 1);
        dis[i] = rsqrtf(df); dinv[i] = 1.0f / df;
        run += d;
    }
    if (tid == T - 1) start[n] = ssum[T - 1];
}
__global__ void k_fill(const int* __restrict__ src, const int* __restrict__ dst,
                       const float* __restrict__ dis, int* cursor, int2* adj, int e)
{
    int i = blockIdx.x * blockDim.x + threadIdx.x;
    if (i >= e) return;
    int s = src[i], d = dst[i];
    int pos = atomicAdd(&cursor[d], 1);
    adj[pos] = make_int2(s, __float_as_int(dis[s] * dis[d]));
}
// W [K,C] fp32 -> W^T [C,K] fp16
__global__ void k_wt(const float* __restrict__ W, __half* __restrict__ WT, int C) {
    int i = blockIdx.x * blockDim.x + threadIdx.x;
    if (i < C * 128) {
        int n = i >> 7, k = i & 127;
        WT[i] = __float2half(W[k * C + n]);
    }
}

// ---------------------------------------------------------------------------
// HMMA GEMM: 128 rows/block, 8 warps * 16 rows, full K=128 resident in smem.
// H fp16; AGG = acc*dinv + bias (fp32 self-loop+bias init).
// smem: Xs [128][136] fp16, Ws [C][136] fp16 (stride 136 -> conflict-free ldm).
// ---------------------------------------------------------------------------
template <int C, bool RELU>
__global__ void __launch_bounds__(256, 2) k_gemm_mma(
    const float* __restrict__ X, const __half* __restrict__ WT,
    const float* __restrict__ bias, const float* __restrict__ dinv,
    __half* __restrict__ H, float* __restrict__ AGG, int nrows)
{
    constexpr int NCH = C / 8;               // n8 chunks (16 or 8)
    constexpr int STR = 136;                 // smem row stride in halves

    extern __shared__ __align__(16) __half smem[];
    __half* Xs = smem;                       // 128 * STR
    __half* Ws = smem + 128 * STR;           // C * STR

    const int tid = threadIdx.x;
    const int l   = tid & 31;
    const int w   = tid >> 5;
    const int m0  = blockIdx.x * 128;

    // ---- load X tile (fp32 -> fp16, optional relu), 128 rows x 32 float4 ----
    #pragma unroll
    for (int it = 0; it < 16; it++) {
        int idx = tid + it * 256;            // 0 .. 4095
        int row = idx >> 5;
        int q   = idx & 31;                  // float4 index within row
        float4 v = make_float4(0.f, 0.f, 0.f, 0.f);
        if (m0 + row < nrows)
            v = *(const float4*)&X[(size_t)(m0 + row) * 128 + q * 4];
        if (RELU) {
            v.x = fmaxf(v.x, 0.f); v.y = fmaxf(v.y, 0.f);
            v.z = fmaxf(v.z, 0.f); v.w = fmaxf(v.w, 0.f);
        }
        __half2 h0 = __floats2half2_rn(v.x, v.y);
        __half2 h1 = __floats2half2_rn(v.z, v.w);
        uint2 pk = make_uint2(*(uint32_t*)&h0, *(uint32_t*)&h1);
        *(uint2*)&Xs[row * STR + q * 4] = pk;
    }
    // ---- load W^T tile (already fp16): C rows x 16 uint4 ----
    #pragma unroll
    for (int it = 0; it < C / 16; it++) {
        int idx = tid + it * 256;            // 0 .. C*16-1
        int n = idx >> 4;
        int q = idx & 15;
        uint4 v = *(const uint4*)&WT[n * 128 + q * 8];
        *(uint4*)&Ws[n * STR + q * 8] = v;
    }
    __syncthreads();

    // ---- compute ----
    float acc[NCH][4];
    #pragma unroll
    for (int c = 0; c < NCH; c++)
        #pragma unroll
        for (int j = 0; j < 4; j++) acc[c][j] = 0.f;

    const uint32_t sX = smem_u32(Xs);
    const uint32_t sW = smem_u32(Ws);
    const int lr = l & 15, lh = l >> 4;
    const uint32_t xbase = sX + (uint32_t)(((w * 16 + lr) * STR + lh * 8) * 2);
    const uint32_t wbase = sW + (uint32_t)((lr * STR + lh * 8) * 2);

    #pragma unroll
    for (int k = 0; k < 8; k++) {
        uint32_t a[4];
        ldm4(a, xbase + k * 32);
        #pragma unroll
        for (int c = 0; c < NCH / 2; c++) {
            uint32_t b[4];
            ldm4(b, wbase + c * (16 * STR * 2) + k * 32);
            mma16816(acc[2 * c],     a, b[0], b[2]);
            mma16816(acc[2 * c + 1], a, b[1], b[3]);
        }
    }

    // ---- epilogue ----
    int r0 = m0 + w * 16 + (l >> 2);
    int r1 = r0 + 8;
    int cb = (l & 3) * 2;
    bool ok0 = r0 < nrows, ok1 = r1 < nrows;
    float di0 = ok0 ? dinv[r0] : 0.f;
    float di1 = ok1 ? dinv[r1] : 0.f;
    #pragma unroll
    for (int c = 0; c < NCH; c++) {
        int col = c * 8 + cb;
        float2 bv = *(const float2*)&bias[col];
        if (ok0) {
            __half2 h = __floats2half2_rn(acc[c][0], acc[c][1]);
            *(__half2*)&H[(size_t)r0 * C + col] = h;
            float2 av = make_float2(fmaf(acc[c][0], di0, bv.x),
                                    fmaf(acc[c][1], di0, bv.y));
            *(float2*)&AGG[(size_t)r0 * C + col] = av;
        }
        if (ok1) {
            __half2 h = __floats2half2_rn(acc[c][2], acc[c][3]);
            *(__half2*)&H[(size_t)r1 * C + col] = h;
            float2 av = make_float2(fmaf(acc[c][2], di1, bv.x),
                                    fmaf(acc[c][3], di1, bv.y));
            *(float2*)&AGG[(size_t)r1 * C + col] = av;
        }
    }
}

// ---------------------------------------------------------------------------
// CSR gather, fp16 H: C/8 lanes per node, uint4 = 8 halves per lane.
// ---------------------------------------------------------------------------
template <int C>
__global__ void __launch_bounds__(256) k_gather(
    const int* __restrict__ start, const int2* __restrict__ adj,
    const __half* __restrict__ H, float* __restrict__ AGG, int n)
{
    constexpr int LPN = C / 8;
    int gt = blockIdx.x * blockDim.x + threadIdx.x;
    int node = gt / LPN;
    int cl = gt % LPN;
    if (node >= n) return;

    int s0 = start[node], s1 = start[node + 1];

    float acc[8];
    {
        float4 a0 = *(const float4*)&AGG[(size_t)node * C + cl * 8];
        float4 a1 = *(const float4*)&AGG[(size_t)node * C + cl * 8 + 4];
        acc[0] = a0.x; acc[1] = a0.y; acc[2] = a0.z; acc[3] = a0.w;
        acc[4] = a1.x; acc[5] = a1.y; acc[6] = a1.z; acc[7] = a1.w;
    }

    int i = s0;
    for (; i + 1 < s1; i += 2) {
        int2 e0 = adj[i], e1 = adj[i + 1];
        float c0 = __int_as_float(e0.y), c1 = __int_as_float(e1.y);
        uint4 h0 = *(const uint4*)&H[(size_t)e0.x * C + cl * 8];
        uint4 h1 = *(const uint4*)&H[(size_t)e1.x * C + cl * 8];
        const uint32_t* p0 = &h0.x;
        const uint32_t* p1 = &h1.x;
        #pragma unroll
        for (int q = 0; q < 4; q++) {
            float2 f0 = __half22float2(*(const __half2*)&p0[q]);
            float2 f1 = __half22float2(*(const __half2*)&p1[q]);
            acc[2 * q + 0] = fmaf(f0.x, c0, fmaf(f1.x, c1, acc[2 * q + 0]));
            acc[2 * q + 1] = fmaf(f0.y, c0, fmaf(f1.y, c1, acc[2 * q + 1]));
        }
    }
    if (i < s1) {
        int2 e0 = adj[i];
        float c0 = __int_as_float(e0.y);
        uint4 h0 = *(const uint4*)&H[(size_t)e0.x * C + cl * 8];
        const uint32_t* p0 = &h0.x;
        #pragma unroll
        for (int q = 0; q < 4; q++) {
            float2 f0 = __half22float2(*(const __half2*)&p0[q]);
            acc[2 * q + 0] = fmaf(f0.x, c0, acc[2 * q + 0]);
            acc[2 * q + 1] = fmaf(f0.y, c0, acc[2 * q + 1]);
        }
    }
    *(float4*)&AGG[(size_t)node * C + cl * 8]     = make_float4(acc[0], acc[1], acc[2], acc[3]);
    *(float4*)&AGG[(size_t)node * C + cl * 8 + 4] = make_float4(acc[4], acc[5], acc[6], acc[7]);
}

// ---------------------------------------------------------------------------
extern "C" void kernel_launch(void* const* d_in, const int* in_sizes, int n_in,
                              void* d_out, int out_size)
{
    const float* x  = (const float*)d_in[0];
    const int*   ei = (const int*)d_in[1];
    const float* W1 = (const float*)d_in[2];
    const float* b1 = (const float*)d_in[3];
    const float* W2 = (const float*)d_in[4];
    const float* b2 = (const float*)d_in[5];
    const float* W3 = (const float*)d_in[6];
    const float* b3 = (const float*)d_in[7];
    float* out = (float*)d_out;

    const int E = in_sizes[1] / 2;
    const int N = in_sizes[0] / 128;
    const int* src = ei;
    const int* dst = ei + E;

    __half *ph, *pwt1, *pwt2, *pwt3;
    float *pa1, *pa2, *pdis, *pdinv;
    int *pdegi, *pstart, *pcursor;
    int2 *padj;
    cudaGetSymbolAddress((void**)&ph,      g_h);
    cudaGetSymbolAddress((void**)&pa1,     g_agg1);
    cudaGetSymbolAddress((void**)&pa2,     g_agg2);
    cudaGetSymbolAddress((void**)&pdis,    g_dis);
    cudaGetSymbolAddress((void**)&pdinv,   g_dinv);
    cudaGetSymbolAddress((void**)&pdegi,   g_degi);
    cudaGetSymbolAddress((void**)&pstart,  g_start);
    cudaGetSymbolAddress((void**)&pcursor, g_cursor);
    cudaGetSymbolAddress((void**)&padj,    g_adj);
    cudaGetSymbolAddress((void**)&pwt1,    g_wt1);
    cudaGetSymbolAddress((void**)&pwt2,    g_wt2);
    cudaGetSymbolAddress((void**)&pwt3,    g_wt3);

    const int SM128 = (128 + 128) * 136 * 2;   // 69632 B
    const int SM64  = (128 + 64) * 136 * 2;    // 52224 B
    cudaFuncSetAttribute(k_gemm_mma<128, false>, cudaFuncAttributeMaxDynamicSharedMemorySize, SM128);
    cudaFuncSetAttribute(k_gemm_mma<128, true>,  cudaFuncAttributeMaxDynamicSharedMemorySize, SM128);
    cudaFuncSetAttribute(k_gemm_mma<64, true>,   cudaFuncAttributeMaxDynamicSharedMemorySize, SM64);

    // CSR build + W^T prep
    cudaMemsetAsync(pdegi, 0, N * sizeof(int));
    k_count<<<(E + 255) / 256, 256>>>(dst, pdegi, E);
    k_wt<<<(128 * 128 + 255) / 256, 256>>>(W1, pwt1, 128);
    k_wt<<<(128 * 128 + 255) / 256, 256>>>(W2, pwt2, 128);
    k_wt<<<(64 * 128 + 255) / 256, 256>>>(W3, pwt3, 64);
    k_scan<<<1, 1024>>>(pdegi, pstart, pcursor, pdis, pdinv, N);
    k_fill<<<(E + 255) / 256, 256>>>(src, dst, pdis, pcursor, padj, E);

    const int gb = (N + 127) / 128;                 // 391
    const int gat128 = (N * 16 + 255) / 256;
    const int gat64  = (N * 8 + 255) / 256;

    k_gemm_mma<128, false><<<gb, 256, SM128>>>(x, pwt1, b1, pdinv, ph, pa1, N);
    k_gather<128><<<gat128, 256>>>(pstart, padj, ph, pa1, N);

    k_gemm_mma<128, true><<<gb, 256, SM128>>>(pa1, pwt2, b2, pdinv, ph, pa2, N);
    k_gather<128><<<gat128, 256>>>(pstart, padj, ph, pa2, N);

    k_gemm_mma<64, true><<<gb, 256, SM64>>>(pa2, pwt3, b3, pdinv, ph, out, N);
    k_gather<64><<<gat64, 256>>>(pstart, padj, ph, out, N);
}

// round 7
// speedup vs baseline: 1.9883x; 1.0290x over previous
#include <cuda_runtime.h>
#include <cuda_fp16.h>
#include <cstdint>

// ---------------------------------------------------------------------------
// 3-layer GCN. HMMA (mma.sync m16n8k16 f16->f32) GEMM + CSR fp16 gather.
// ---------------------------------------------------------------------------

#define NN 50000
#define EE 640000

__device__ __half g_h[NN * 128];     // linear output, fp16
__device__ float  g_agg1[NN * 128];
__device__ float  g_agg2[NN * 128];
__device__ float  g_dis[NN];
__device__ float  g_dinv[NN];
__device__ int    g_degi[NN];
__device__ int    g_start[NN + 1];
__device__ int    g_cursor[NN];
__device__ int2   g_adj[EE];
__device__ __half g_wt1[128 * 128];  // W^T fp16 [C][K]
__device__ __half g_wt2[128 * 128];
__device__ __half g_wt3[64 * 128];

__device__ __forceinline__ uint32_t smem_u32(const void* p) {
    uint32_t a;
    asm("{ .reg .u64 t; cvta.to.shared.u64 t, %1; cvt.u32.u64 %0, t; }"
        : "=r"(a) : "l"(p));
    return a;
}
__device__ __forceinline__ void ldm4(uint32_t* r, uint32_t addr) {
    asm volatile("ldmatrix.sync.aligned.m8n8.x4.shared.b16 {%0,%1,%2,%3}, [%4];"
                 : "=r"(r[0]), "=r"(r[1]), "=r"(r[2]), "=r"(r[3]) : "r"(addr));
}
__device__ __forceinline__ void mma16816(float* d, const uint32_t* a,
                                         uint32_t b0, uint32_t b1) {
    asm volatile(
        "mma.sync.aligned.m16n8k16.row.col.f32.f16.f16.f32 "
        "{%0,%1,%2,%3}, {%4,%5,%6,%7}, {%8,%9}, {%0,%1,%2,%3};"
        : "+f"(d[0]), "+f"(d[1]), "+f"(d[2]), "+f"(d[3])
        : "r"(a[0]), "r"(a[1]), "r"(a[2]), "r"(a[3]), "r"(b0), "r"(b1));
}

// ---------------------------------------------------------------------------
// degree + CSR build + weight transpose
// ---------------------------------------------------------------------------
__global__ void k_count(const int* __restrict__ dst, int* degi, int e) {
    int i = blockIdx.x * blockDim.x + threadIdx.x;
    if (i < e) atomicAdd(&degi[dst[i]], 1);
}
__global__ void __launch_bounds__(1024) k_scan(
    const int* __restrict__ degi, int* start, int* cursor,
    float* dis, float* dinv, int n)
{
    const int T = 1024;
    int tid = threadIdx.x;
    int chunk = (n + T - 1) / T;
    int lo = tid * chunk, hi = min(lo + chunk, n);
    int sum = 0;
    for (int i = lo; i < hi; i++) sum += degi[i];
    __shared__ int ssum[T];
    ssum[tid] = sum;
    __syncthreads();
    for (int off = 1; off < T; off *= 2) {
        int v = (tid >= off) ? ssum[tid - off] : 0;
        __syncthreads();
        ssum[tid] += v;
        __syncthreads();
    }
    int run = (tid == 0) ? 0 : ssum[tid - 1];
    for (int i = lo; i < hi; i++) {
        int d = degi[i];
        start[i] = run; cursor[i] = run;
        float df = (float)(d + 1);
        dis[i] = rsqrtf(df); dinv[i] = 1.0f / df;
        run += d;
    }
    if (tid == T - 1) start[n] = ssum[T - 1];
}
__global__ void k_fill(const int* __restrict__ src, const int* __restrict__ dst,
                       const float* __restrict__ dis, int* cursor, int2* adj, int e)
{
    int i = blockIdx.x * blockDim.x + threadIdx.x;
    if (i >= e) return;
    int s = src[i], d = dst[i];
    int pos = atomicAdd(&cursor[d], 1);
    adj[pos] = make_int2(s, __float_as_int(dis[s] * dis[d]));
}
// all 3 weight transposes (fp32 [K,C] -> fp16 [C,K]) in one launch
__global__ void k_wt_all(const float* __restrict__ W1, const float* __restrict__ W2,
                         const float* __restrict__ W3, __half* __restrict__ T1,
                         __half* __restrict__ T2, __half* __restrict__ T3)
{
    int i = blockIdx.x * blockDim.x + threadIdx.x;
    if (i < 16384) {
        int n = i >> 7, k = i & 127;
        T1[i] = __float2half(W1[k * 128 + n]);
    } else if (i < 32768) {
        int j = i - 16384, n = j >> 7, k = j & 127;
        T2[j] = __float2half(W2[k * 128 + n]);
    } else if (i < 40960) {
        int j = i - 32768, n = j >> 7, k = j & 127;
        T3[j] = __float2half(W3[k * 64 + n]);
    }
}

// ---------------------------------------------------------------------------
// HMMA GEMM: 128 rows/block, 8 warps * 16 rows, full K=128 resident in smem.
// ---------------------------------------------------------------------------
template <int C, bool RELU>
__global__ void __launch_bounds__(256, 2) k_gemm_mma(
    const float* __restrict__ X, const __half* __restrict__ WT,
    const float* __restrict__ bias, const float* __restrict__ dinv,
    __half* __restrict__ H, float* __restrict__ AGG, int nrows)
{
    constexpr int NCH = C / 8;
    constexpr int STR = 136;

    extern __shared__ __align__(16) __half smem[];
    __half* Xs = smem;                       // 128 * STR
    __half* Ws = smem + 128 * STR;           // C * STR

    const int tid = threadIdx.x;
    const int l   = tid & 31;
    const int w   = tid >> 5;
    const int m0  = blockIdx.x * 128;

    #pragma unroll
    for (int it = 0; it < 16; it++) {
        int idx = tid + it * 256;
        int row = idx >> 5;
        int q   = idx & 31;
        float4 v = make_float4(0.f, 0.f, 0.f, 0.f);
        if (m0 + row < nrows)
            v = *(const float4*)&X[(size_t)(m0 + row) * 128 + q * 4];
        if (RELU) {
            v.x = fmaxf(v.x, 0.f); v.y = fmaxf(v.y, 0.f);
            v.z = fmaxf(v.z, 0.f); v.w = fmaxf(v.w, 0.f);
        }
        __half2 h0 = __floats2half2_rn(v.x, v.y);
        __half2 h1 = __floats2half2_rn(v.z, v.w);
        uint2 pk = make_uint2(*(uint32_t*)&h0, *(uint32_t*)&h1);
        *(uint2*)&Xs[row * STR + q * 4] = pk;
    }
    #pragma unroll
    for (int it = 0; it < C / 16; it++) {
        int idx = tid + it * 256;
        int n = idx >> 4;
        int q = idx & 15;
        uint4 v = *(const uint4*)&WT[n * 128 + q * 8];
        *(uint4*)&Ws[n * STR + q * 8] = v;
    }
    __syncthreads();

    float acc[NCH][4];
    #pragma unroll
    for (int c = 0; c < NCH; c++)
        #pragma unroll
        for (int j = 0; j < 4; j++) acc[c][j] = 0.f;

    const uint32_t sX = smem_u32(Xs);
    const uint32_t sW = smem_u32(Ws);
    const int lr = l & 15, lh = l >> 4;
    const uint32_t xbase = sX + (uint32_t)(((w * 16 + lr) * STR + lh * 8) * 2);
    const uint32_t wbase = sW + (uint32_t)((lr * STR + lh * 8) * 2);

    #pragma unroll
    for (int k = 0; k < 8; k++) {
        uint32_t a[4];
        ldm4(a, xbase + k * 32);
        #pragma unroll
        for (int c = 0; c < NCH / 2; c++) {
            uint32_t b[4];
            ldm4(b, wbase + c * (16 * STR * 2) + k * 32);
            mma16816(acc[2 * c],     a, b[0], b[2]);
            mma16816(acc[2 * c + 1], a, b[1], b[3]);
        }
    }

    int r0 = m0 + w * 16 + (l >> 2);
    int r1 = r0 + 8;
    int cb = (l & 3) * 2;
    bool ok0 = r0 < nrows, ok1 = r1 < nrows;
    float di0 = ok0 ? dinv[r0] : 0.f;
    float di1 = ok1 ? dinv[r1] : 0.f;
    #pragma unroll
    for (int c = 0; c < NCH; c++) {
        int col = c * 8 + cb;
        float2 bv = *(const float2*)&bias[col];
        if (ok0) {
            __half2 h = __floats2half2_rn(acc[c][0], acc[c][1]);
            *(__half2*)&H[(size_t)r0 * C + col] = h;
            float2 av = make_float2(fmaf(acc[c][0], di0, bv.x),
                                    fmaf(acc[c][1], di0, bv.y));
            *(float2*)&AGG[(size_t)r0 * C + col] = av;
        }
        if (ok1) {
            __half2 h = __floats2half2_rn(acc[c][2], acc[c][3]);
            *(__half2*)&H[(size_t)r1 * C + col] = h;
            float2 av = make_float2(fmaf(acc[c][2], di1, bv.x),
                                    fmaf(acc[c][3], di1, bv.y));
            *(float2*)&AGG[(size_t)r1 * C + col] = av;
        }
    }
}

// ---------------------------------------------------------------------------
// CSR gather, fp16 H: C/8 lanes per node; 4-way unrolled edge loop for MLP.
// ---------------------------------------------------------------------------
template <int C>
__global__ void __launch_bounds__(256) k_gather(
    const int* __restrict__ start, const int2* __restrict__ adj,
    const __half* __restrict__ H, float* __restrict__ AGG, int n)
{
    constexpr int LPN = C / 8;
    int gt = blockIdx.x * blockDim.x + threadIdx.x;
    int node = gt / LPN;
    int cl = gt % LPN;
    if (node >= n) return;

    int s0 = start[node], s1 = start[node + 1];

    float acc[8];
    {
        float4 a0 = *(const float4*)&AGG[(size_t)node * C + cl * 8];
        float4 a1 = *(const float4*)&AGG[(size_t)node * C + cl * 8 + 4];
        acc[0] = a0.x; acc[1] = a0.y; acc[2] = a0.z; acc[3] = a0.w;
        acc[4] = a1.x; acc[5] = a1.y; acc[6] = a1.z; acc[7] = a1.w;
    }

    int i = s0;
    for (; i + 3 < s1; i += 4) {
        int2 e0 = adj[i], e1 = adj[i + 1], e2 = adj[i + 2], e3 = adj[i + 3];
        float c0 = __int_as_float(e0.y), c1 = __int_as_float(e1.y);
        float c2 = __int_as_float(e2.y), c3 = __int_as_float(e3.y);
        uint4 h0 = *(const uint4*)&H[(size_t)e0.x * C + cl * 8];
        uint4 h1 = *(const uint4*)&H[(size_t)e1.x * C + cl * 8];
        uint4 h2 = *(const uint4*)&H[(size_t)e2.x * C + cl * 8];
        uint4 h3 = *(const uint4*)&H[(size_t)e3.x * C + cl * 8];
        const uint32_t* p0 = &h0.x;
        const uint32_t* p1 = &h1.x;
        const uint32_t* p2 = &h2.x;
        const uint32_t* p3 = &h3.x;
        #pragma unroll
        for (int q = 0; q < 4; q++) {
            float2 f0 = __half22float2(*(const __half2*)&p0[q]);
            float2 f1 = __half22float2(*(const __half2*)&p1[q]);
            float2 f2 = __half22float2(*(const __half2*)&p2[q]);
            float2 f3 = __half22float2(*(const __half2*)&p3[q]);
            acc[2 * q + 0] = fmaf(f0.x, c0, acc[2 * q + 0]);
            acc[2 * q + 1] = fmaf(f0.y, c0, acc[2 * q + 1]);
            acc[2 * q + 0] = fmaf(f1.x, c1, acc[2 * q + 0]);
            acc[2 * q + 1] = fmaf(f1.y, c1, acc[2 * q + 1]);
            acc[2 * q + 0] = fmaf(f2.x, c2, acc[2 * q + 0]);
            acc[2 * q + 1] = fmaf(f2.y, c2, acc[2 * q + 1]);
            acc[2 * q + 0] = fmaf(f3.x, c3, acc[2 * q + 0]);
            acc[2 * q + 1] = fmaf(f3.y, c3, acc[2 * q + 1]);
        }
    }
    for (; i < s1; i++) {
        int2 e0 = adj[i];
        float c0 = __int_as_float(e0.y);
        uint4 h0 = *(const uint4*)&H[(size_t)e0.x * C + cl * 8];
        const uint32_t* p0 = &h0.x;
        #pragma unroll
        for (int q = 0; q < 4; q++) {
            float2 f0 = __half22float2(*(const __half2*)&p0[q]);
            acc[2 * q + 0] = fmaf(f0.x, c0, acc[2 * q + 0]);
            acc[2 * q + 1] = fmaf(f0.y, c0, acc[2 * q + 1]);
        }
    }
    *(float4*)&AGG[(size_t)node * C + cl * 8]     = make_float4(acc[0], acc[1], acc[2], acc[3]);
    *(float4*)&AGG[(size_t)node * C + cl * 8 + 4] = make_float4(acc[4], acc[5], acc[6], acc[7]);
}

// ---------------------------------------------------------------------------
extern "C" void kernel_launch(void* const* d_in, const int* in_sizes, int n_in,
                              void* d_out, int out_size)
{
    const float* x  = (const float*)d_in[0];
    const int*   ei = (const int*)d_in[1];
    const float* W1 = (const float*)d_in[2];
    const float* b1 = (const float*)d_in[3];
    const float* W2 = (const float*)d_in[4];
    const float* b2 = (const float*)d_in[5];
    const float* W3 = (const float*)d_in[6];
    const float* b3 = (const float*)d_in[7];
    float* out = (float*)d_out;

    const int E = in_sizes[1] / 2;
    const int N = in_sizes[0] / 128;
    const int* src = ei;
    const int* dst = ei + E;

    __half *ph, *pwt1, *pwt2, *pwt3;
    float *pa1, *pa2, *pdis, *pdinv;
    int *pdegi, *pstart, *pcursor;
    int2 *padj;
    cudaGetSymbolAddress((void**)&ph,      g_h);
    cudaGetSymbolAddress((void**)&pa1,     g_agg1);
    cudaGetSymbolAddress((void**)&pa2,     g_agg2);
    cudaGetSymbolAddress((void**)&pdis,    g_dis);
    cudaGetSymbolAddress((void**)&pdinv,   g_dinv);
    cudaGetSymbolAddress((void**)&pdegi,   g_degi);
    cudaGetSymbolAddress((void**)&pstart,  g_start);
    cudaGetSymbolAddress((void**)&pcursor, g_cursor);
    cudaGetSymbolAddress((void**)&padj,    g_adj);
    cudaGetSymbolAddress((void**)&pwt1,    g_wt1);
    cudaGetSymbolAddress((void**)&pwt2,    g_wt2);
    cudaGetSymbolAddress((void**)&pwt3,    g_wt3);

    const int SM128 = (128 + 128) * 136 * 2;   // 69632 B
    const int SM64  = (128 + 64) * 136 * 2;    // 52224 B
    cudaFuncSetAttribute(k_gemm_mma<128, false>, cudaFuncAttributeMaxDynamicSharedMemorySize, SM128);
    cudaFuncSetAttribute(k_gemm_mma<128, true>,  cudaFuncAttributeMaxDynamicSharedMemorySize, SM128);
    cudaFuncSetAttribute(k_gemm_mma<64, true>,   cudaFuncAttributeMaxDynamicSharedMemorySize, SM64);

    // CSR build + W^T prep
    cudaMemsetAsync(pdegi, 0, N * sizeof(int));
    k_count<<<(E + 255) / 256, 256>>>(dst, pdegi, E);
    k_wt_all<<<(40960 + 255) / 256, 256>>>(W1, W2, W3, pwt1, pwt2, pwt3);
    k_scan<<<1, 1024>>>(pdegi, pstart, pcursor, pdis, pdinv, N);
    k_fill<<<(E + 255) / 256, 256>>>(src, dst, pdis, pcursor, padj, E);

    const int gb = (N + 127) / 128;
    const int gat128 = (N * 16 + 255) / 256;
    const int gat64  = (N * 8 + 255) / 256;

    k_gemm_mma<128, false><<<gb, 256, SM128>>>(x, pwt1, b1, pdinv, ph, pa1, N);
    k_gather<128><<<gat128, 256>>>(pstart, padj, ph, pa1, N);

    k_gemm_mma<128, true><<<gb, 256, SM128>>>(pa1, pwt2, b2, pdinv, ph, pa2, N);
    k_gather<128><<<gat128, 256>>>(pstart, padj, ph, pa2, N);

    k_gemm_mma<64, true><<<gb, 256, SM64>>>(pa2, pwt3, b3, pdinv, ph, out, N);
    k_gather<64><<<gat64, 256>>>(pstart, padj, ph, out, N);
}

// round 8
// speedup vs baseline: 3.7332x; 1.8776x over previous
#include <cuda_runtime.h>
#include <cuda_fp16.h>
#include <cstdint>

// ---------------------------------------------------------------------------
// 3-layer GCN. HMMA GEMM + CSR fp16 gather (warp/node) + parallel CSR build.
// ---------------------------------------------------------------------------

#define NN 50000
#define EE 640000
#define SCB 256                       // scan block size
#define NSC ((NN + SCB - 1) / SCB)    // scan blocks (196)

__device__ __half g_h[NN * 128];
__device__ float  g_agg1[NN * 128];
__device__ float  g_agg2[NN * 128];
__device__ float  g_dis[NN];
__device__ float  g_dinv[NN];
__device__ int    g_degi[NN];
__device__ int    g_bsum[NSC];
__device__ int    g_start[NN + 1];
__device__ int    g_cursor[NN];
__device__ int2   g_adj[EE];
__device__ __half g_wt1[128 * 128];
__device__ __half g_wt2[128 * 128];
__device__ __half g_wt3[64 * 128];

__device__ __forceinline__ uint32_t smem_u32(const void* p) {
    uint32_t a;
    asm("{ .reg .u64 t; cvta.to.shared.u64 t, %1; cvt.u32.u64 %0, t; }"
        : "=r"(a) : "l"(p));
    return a;
}
__device__ __forceinline__ void ldm4(uint32_t* r, uint32_t addr) {
    asm volatile("ldmatrix.sync.aligned.m8n8.x4.shared.b16 {%0,%1,%2,%3}, [%4];"
                 : "=r"(r[0]), "=r"(r[1]), "=r"(r[2]), "=r"(r[3]) : "r"(addr));
}
__device__ __forceinline__ void mma16816(float* d, const uint32_t* a,
                                         uint32_t b0, uint32_t b1) {
    asm volatile(
        "mma.sync.aligned.m16n8k16.row.col.f32.f16.f16.f32 "
        "{%0,%1,%2,%3}, {%4,%5,%6,%7}, {%8,%9}, {%0,%1,%2,%3};"
        : "+f"(d[0]), "+f"(d[1]), "+f"(d[2]), "+f"(d[3])
        : "r"(a[0]), "r"(a[1]), "r"(a[2]), "r"(a[3]), "r"(b0), "r"(b1));
}

// ---------------------------------------------------------------------------
// CSR build (parallel): count -> block sums -> scan sums -> emit offsets -> fill
// ---------------------------------------------------------------------------
__global__ void k_count(const int* __restrict__ dst, int* degi, int e) {
    int i = blockIdx.x * blockDim.x + threadIdx.x;
    if (i < e) atomicAdd(&degi[dst[i]], 1);
}
__global__ void k_bsum(const int* __restrict__ degi, int* bsum, int n) {
    __shared__ int s[SCB];
    int i = blockIdx.x * SCB + threadIdx.x;
    s[threadIdx.x] = (i < n) ? degi[i] : 0;
    __syncthreads();
    for (int off = SCB / 2; off > 0; off >>= 1) {
        if (threadIdx.x < off) s[threadIdx.x] += s[threadIdx.x + off];
        __syncthreads();
    }
    if (threadIdx.x == 0) bsum[blockIdx.x] = s[0];
}
// exclusive scan of NSC block sums (single small block)
__global__ void k_scan_mid(int* bsum) {
    __shared__ int s[SCB];
    int t = threadIdx.x;
    s[t] = (t < NSC) ? bsum[t] : 0;
    __syncthreads();
    for (int off = 1; off < SCB; off *= 2) {
        int v = (t >= off) ? s[t - off] : 0;
        __syncthreads();
        s[t] += v;
        __syncthreads();
    }
    if (t < NSC) bsum[t] = s[t] - ((t < NSC) ? ((t == 0) ? s[0] : s[t] - s[t - 1]) : 0) * 0 - (t == 0 ? s[0] : s[t] - s[t - 1]); // exclusive = inclusive - self
    // simpler: exclusive[t] = inclusive[t] - orig[t]; orig = inclusive - inclusive_prev
    // rewritten below for clarity:
    if (t < NSC) bsum[t] = (t == 0) ? 0 : s[t - 1];
}
__global__ void k_scan_emit(const int* __restrict__ degi, const int* __restrict__ bsum,
                            int* start, int* cursor, float* dis, float* dinv, int n)
{
    __shared__ int s[SCB];
    int i = blockIdx.x * SCB + threadIdx.x;
    int t = threadIdx.x;
    int d = (i < n) ? degi[i] : 0;
    s[t] = d;
    __syncthreads();
    for (int off = 1; off < SCB; off *= 2) {
        int v = (t >= off) ? s[t - off] : 0;
        __syncthreads();
        s[t] += v;
        __syncthreads();
    }
    if (i < n) {
        int run = bsum[blockIdx.x] + s[t] - d;   // exclusive
        start[i]  = run;
        cursor[i] = run;
        float df = (float)(d + 1);
        dis[i]  = rsqrtf(df);
        dinv[i] = 1.0f / df;
        if (i == n - 1) start[n] = run + d;
    }
}
__global__ void k_fill(const int* __restrict__ src, const int* __restrict__ dst,
                       const float* __restrict__ dis, int* cursor, int2* adj, int e)
{
    int i = blockIdx.x * blockDim.x + threadIdx.x;
    if (i >= e) return;
    int s = src[i], d = dst[i];
    int pos = atomicAdd(&cursor[d], 1);
    adj[pos] = make_int2(s, __float_as_int(dis[s] * dis[d]));
}
__global__ void k_wt_all(const float* __restrict__ W1, const float* __restrict__ W2,
                         const float* __restrict__ W3, __half* __restrict__ T1,
                         __half* __restrict__ T2, __half* __restrict__ T3)
{
    int i = blockIdx.x * blockDim.x + threadIdx.x;
    if (i < 16384) {
        int n = i >> 7, k = i & 127;
        T1[i] = __float2half(W1[k * 128 + n]);
    } else if (i < 32768) {
        int j = i - 16384, n = j >> 7, k = j & 127;
        T2[j] = __float2half(W2[k * 128 + n]);
    } else if (i < 40960) {
        int j = i - 32768, n = j >> 7, k = j & 127;
        T3[j] = __float2half(W3[k * 64 + n]);
    }
}

// ---------------------------------------------------------------------------
// HMMA GEMM (unchanged from R7)
// ---------------------------------------------------------------------------
template <int C, bool RELU>
__global__ void __launch_bounds__(256, 2) k_gemm_mma(
    const float* __restrict__ X, const __half* __restrict__ WT,
    const float* __restrict__ bias, const float* __restrict__ dinv,
    __half* __restrict__ H, float* __restrict__ AGG, int nrows)
{
    constexpr int NCH = C / 8;
    constexpr int STR = 136;

    extern __shared__ __align__(16) __half smem[];
    __half* Xs = smem;
    __half* Ws = smem + 128 * STR;

    const int tid = threadIdx.x;
    const int l   = tid & 31;
    const int w   = tid >> 5;
    const int m0  = blockIdx.x * 128;

    #pragma unroll
    for (int it = 0; it < 16; it++) {
        int idx = tid + it * 256;
        int row = idx >> 5;
        int q   = idx & 31;
        float4 v = make_float4(0.f, 0.f, 0.f, 0.f);
        if (m0 + row < nrows)
            v = *(const float4*)&X[(size_t)(m0 + row) * 128 + q * 4];
        if (RELU) {
            v.x = fmaxf(v.x, 0.f); v.y = fmaxf(v.y, 0.f);
            v.z = fmaxf(v.z, 0.f); v.w = fmaxf(v.w, 0.f);
        }
        __half2 h0 = __floats2half2_rn(v.x, v.y);
        __half2 h1 = __floats2half2_rn(v.z, v.w);
        uint2 pk = make_uint2(*(uint32_t*)&h0, *(uint32_t*)&h1);
        *(uint2*)&Xs[row * STR + q * 4] = pk;
    }
    #pragma unroll
    for (int it = 0; it < C / 16; it++) {
        int idx = tid + it * 256;
        int n = idx >> 4;
        int q = idx & 15;
        uint4 v = *(const uint4*)&WT[n * 128 + q * 8];
        *(uint4*)&Ws[n * STR + q * 8] = v;
    }
    __syncthreads();

    float acc[NCH][4];
    #pragma unroll
    for (int c = 0; c < NCH; c++)
        #pragma unroll
        for (int j = 0; j < 4; j++) acc[c][j] = 0.f;

    const uint32_t sX = smem_u32(Xs);
    const uint32_t sW = smem_u32(Ws);
    const int lr = l & 15, lh = l >> 4;
    const uint32_t xbase = sX + (uint32_t)(((w * 16 + lr) * STR + lh * 8) * 2);
    const uint32_t wbase = sW + (uint32_t)((lr * STR + lh * 8) * 2);

    #pragma unroll
    for (int k = 0; k < 8; k++) {
        uint32_t a[4];
        ldm4(a, xbase + k * 32);
        #pragma unroll
        for (int c = 0; c < NCH / 2; c++) {
            uint32_t b[4];
            ldm4(b, wbase + c * (16 * STR * 2) + k * 32);
            mma16816(acc[2 * c],     a, b[0], b[2]);
            mma16816(acc[2 * c + 1], a, b[1], b[3]);
        }
    }

    int r0 = m0 + w * 16 + (l >> 2);
    int r1 = r0 + 8;
    int cb = (l & 3) * 2;
    bool ok0 = r0 < nrows, ok1 = r1 < nrows;
    float di0 = ok0 ? dinv[r0] : 0.f;
    float di1 = ok1 ? dinv[r1] : 0.f;
    #pragma unroll
    for (int c = 0; c < NCH; c++) {
        int col = c * 8 + cb;
        float2 bv = *(const float2*)&bias[col];
        if (ok0) {
            __half2 h = __floats2half2_rn(acc[c][0], acc[c][1]);
            *(__half2*)&H[(size_t)r0 * C + col] = h;
            float2 av = make_float2(fmaf(acc[c][0], di0, bv.x),
                                    fmaf(acc[c][1], di0, bv.y));
            *(float2*)&AGG[(size_t)r0 * C + col] = av;
        }
        if (ok1) {
            __half2 h = __floats2half2_rn(acc[c][2], acc[c][3]);
            *(__half2*)&H[(size_t)r1 * C + col] = h;
            float2 av = make_float2(fmaf(acc[c][2], di1, bv.x),
                                    fmaf(acc[c][3], di1, bv.y));
            *(float2*)&AGG[(size_t)r1 * C + col] = av;
        }
    }
}

// ---------------------------------------------------------------------------
// CSR gather: ONE WARP PER NODE. C=128: lane uint2 (4 halves); C=64: lane uint.
// 4-wide unrolled edge loop, adj broadcast loads.
// ---------------------------------------------------------------------------
template <int C>
__global__ void __launch_bounds__(256) k_gather(
    const int* __restrict__ start, const int2* __restrict__ adj,
    const __half* __restrict__ H, float* __restrict__ AGG, int n)
{
    int node = (blockIdx.x * blockDim.x + threadIdx.x) >> 5;
    int lane = threadIdx.x & 31;
    if (node >= n) return;

    int s0 = start[node], s1 = start[node + 1];

    if (C == 128) {
        float4 acc = *(const float4*)&AGG[(size_t)node * 128 + lane * 4];
        int i = s0;
        for (; i + 3 < s1; i += 4) {
            int2 e0 = adj[i], e1 = adj[i + 1], e2 = adj[i + 2], e3 = adj[i + 3];
            uint2 h0 = *(const uint2*)&H[(size_t)e0.x * 128 + lane * 4];
            uint2 h1 = *(const uint2*)&H[(size_t)e1.x * 128 + lane * 4];
            uint2 h2 = *(const uint2*)&H[(size_t)e2.x * 128 + lane * 4];
            uint2 h3 = *(const uint2*)&H[(size_t)e3.x * 128 + lane * 4];
            float c0 = __int_as_float(e0.y), c1 = __int_as_float(e1.y);
            float c2 = __int_as_float(e2.y), c3 = __int_as_float(e3.y);
            float2 a0 = __half22float2(*(const __half2*)&h0.x);
            float2 b0 = __half22float2(*(const __half2*)&h0.y);
            float2 a1 = __half22float2(*(const __half2*)&h1.x);
            float2 b1 = __half22float2(*(const __half2*)&h1.y);
            float2 a2 = __half22float2(*(const __half2*)&h2.x);
            float2 b2 = __half22float2(*(const __half2*)&h2.y);
            float2 a3 = __half22float2(*(const __half2*)&h3.x);
            float2 b3 = __half22float2(*(const __half2*)&h3.y);
            acc.x = fmaf(a0.x, c0, fmaf(a1.x, c1, fmaf(a2.x, c2, fmaf(a3.x, c3, acc.x))));
            acc.y = fmaf(a0.y, c0, fmaf(a1.y, c1, fmaf(a2.y, c2, fmaf(a3.y, c3, acc.y))));
            acc.z = fmaf(b0.x, c0, fmaf(b1.x, c1, fmaf(b2.x, c2, fmaf(b3.x, c3, acc.z))));
            acc.w = fmaf(b0.y, c0, fmaf(b1.y, c1, fmaf(b2.y, c2, fmaf(b3.y, c3, acc.w))));
        }
        for (; i < s1; i++) {
            int2 e0 = adj[i];
            uint2 h0 = *(const uint2*)&H[(size_t)e0.x * 128 + lane * 4];
            float c0 = __int_as_float(e0.y);
            float2 a0 = __half22float2(*(const __half2*)&h0.x);
            float2 b0 = __half22float2(*(const __half2*)&h0.y);
            acc.x = fmaf(a0.x, c0, acc.x);
            acc.y = fmaf(a0.y, c0, acc.y);
            acc.z = fmaf(b0.x, c0, acc.z);
            acc.w = fmaf(b0.y, c0, acc.w);
        }
        *(float4*)&AGG[(size_t)node * 128 + lane * 4] = acc;
    } else {
        float2 acc = *(const float2*)&AGG[(size_t)node * 64 + lane * 2];
        int i = s0;
        for (; i + 3 < s1; i += 4) {
            int2 e0 = adj[i], e1 = adj[i + 1], e2 = adj[i + 2], e3 = adj[i + 3];
            uint32_t h0 = *(const uint32_t*)&H[(size_t)e0.x * 64 + lane * 2];
            uint32_t h1 = *(const uint32_t*)&H[(size_t)e1.x * 64 + lane * 2];
            uint32_t h2 = *(const uint32_t*)&H[(size_t)e2.x * 64 + lane * 2];
            uint32_t h3 = *(const uint32_t*)&H[(size_t)e3.x * 64 + lane * 2];
            float c0 = __int_as_float(e0.y), c1 = __int_as_float(e1.y);
            float c2 = __int_as_float(e2.y), c3 = __int_as_float(e3.y);
            float2 a0 = __half22float2(*(const __half2*)&h0);
            float2 a1 = __half22float2(*(const __half2*)&h1);
            float2 a2 = __half22float2(*(const __half2*)&h2);
            float2 a3 = __half22float2(*(const __half2*)&h3);
            acc.x = fmaf(a0.x, c0, fmaf(a1.x, c1, fmaf(a2.x, c2, fmaf(a3.x, c3, acc.x))));
            acc.y = fmaf(a0.y, c0, fmaf(a1.y, c1, fmaf(a2.y, c2, fmaf(a3.y, c3, acc.y))));
        }
        for (; i < s1; i++) {
            int2 e0 = adj[i];
            uint32_t h0 = *(const uint32_t*)&H[(size_t)e0.x * 64 + lane * 2];
            float c0 = __int_as_float(e0.y);
            float2 a0 = __half22float2(*(const __half2*)&h0);
            acc.x = fmaf(a0.x, c0, acc.x);
            acc.y = fmaf(a0.y, c0, acc.y);
        }
        *(float2*)&AGG[(size_t)node * 64 + lane * 2] = acc;
    }
}

// ---------------------------------------------------------------------------
extern "C" void kernel_launch(void* const* d_in, const int* in_sizes, int n_in,
                              void* d_out, int out_size)
{
    const float* x  = (const float*)d_in[0];
    const int*   ei = (const int*)d_in[1];
    const float* W1 = (const float*)d_in[2];
    const float* b1 = (const float*)d_in[3];
    const float* W2 = (const float*)d_in[4];
    const float* b2 = (const float*)d_in[5];
    const float* W3 = (const float*)d_in[6];
    const float* b3 = (const float*)d_in[7];
    float* out = (float*)d_out;

    const int E = in_sizes[1] / 2;
    const int N = in_sizes[0] / 128;
    const int* src = ei;
    const int* dst = ei + E;

    __half *ph, *pwt1, *pwt2, *pwt3;
    float *pa1, *pa2, *pdis, *pdinv;
    int *pdegi, *pbsum, *pstart, *pcursor;
    int2 *padj;
    cudaGetSymbolAddress((void**)&ph,      g_h);
    cudaGetSymbolAddress((void**)&pa1,     g_agg1);
    cudaGetSymbolAddress((void**)&pa2,     g_agg2);
    cudaGetSymbolAddress((void**)&pdis,    g_dis);
    cudaGetSymbolAddress((void**)&pdinv,   g_dinv);
    cudaGetSymbolAddress((void**)&pdegi,   g_degi);
    cudaGetSymbolAddress((void**)&pbsum,   g_bsum);
    cudaGetSymbolAddress((void**)&pstart,  g_start);
    cudaGetSymbolAddress((void**)&pcursor, g_cursor);
    cudaGetSymbolAddress((void**)&padj,    g_adj);
    cudaGetSymbolAddress((void**)&pwt1,    g_wt1);
    cudaGetSymbolAddress((void**)&pwt2,    g_wt2);
    cudaGetSymbolAddress((void**)&pwt3,    g_wt3);

    const int SM128 = (128 + 128) * 136 * 2;
    const int SM64  = (128 + 64) * 136 * 2;
    cudaFuncSetAttribute(k_gemm_mma<128, false>, cudaFuncAttributeMaxDynamicSharedMemorySize, SM128);
    cudaFuncSetAttribute(k_gemm_mma<128, true>,  cudaFuncAttributeMaxDynamicSharedMemorySize, SM128);
    cudaFuncSetAttribute(k_gemm_mma<64, true>,   cudaFuncAttributeMaxDynamicSharedMemorySize, SM64);

    // CSR build + W^T prep
    cudaMemsetAsync(pdegi, 0, N * sizeof(int));
    k_count<<<(E + 255) / 256, 256>>>(dst, pdegi, E);
    k_wt_all<<<(40960 + 255) / 256, 256>>>(W1, W2, W3, pwt1, pwt2, pwt3);
    k_bsum<<<NSC, SCB>>>(pdegi, pbsum, N);
    k_scan_mid<<<1, SCB>>>(pbsum);
    k_scan_emit<<<NSC, SCB>>>(pdegi, pbsum, pstart, pcursor, pdis, pdinv, N);
    k_fill<<<(E + 255) / 256, 256>>>(src, dst, pdis, pcursor, padj, E);

    const int gb = (N + 127) / 128;
    const int gatb = (N * 32 + 255) / 256;

    k_gemm_mma<128, false><<<gb, 256, SM128>>>(x, pwt1, b1, pdinv, ph, pa1, N);
    k_gather<128><<<gatb, 256>>>(pstart, padj, ph, pa1, N);

    k_gemm_mma<128, true><<<gb, 256, SM128>>>(pa1, pwt2, b2, pdinv, ph, pa2, N);
    k_gather<128><<<gatb, 256>>>(pstart, padj, ph, pa2, N);

    k_gemm_mma<64, true><<<gb, 256, SM64>>>(pa2, pwt3, b3, pdinv, ph, out, N);
    k_gather<64><<<gatb, 256>>>(pstart, padj, ph, out, N);
}

// round 9
// speedup vs baseline: 4.4130x; 1.1821x over previous
#include <cuda_runtime.h>
#include <cuda_fp16.h>
#include <cstdint>

// ---------------------------------------------------------------------------
// 3-layer GCN. HMMA GEMM (H fp16 only) + CSR gather computing self-term,
// fp16 inter-layer activations, ReLU fused into gather store.
// ---------------------------------------------------------------------------

#define NN 50000
#define EE 640000
#define SCB 256
#define NSC ((NN + SCB - 1) / SCB)

__device__ __half g_h[NN * 128];     // per-layer GEMM output
__device__ __half g_agg1[NN * 128];  // relu(layer1 agg) fp16
__device__ __half g_agg2[NN * 128];  // relu(layer2 agg) fp16
__device__ float  g_dis[NN];
__device__ float  g_dinv[NN];
__device__ int    g_degi[NN];
__device__ int    g_bsum[NSC];
__device__ int    g_start[NN + 1];
__device__ int    g_cursor[NN];
__device__ int2   g_adj[EE];
__device__ __half g_wt1[128 * 128];
__device__ __half g_wt2[128 * 128];
__device__ __half g_wt3[64 * 128];

__device__ __forceinline__ uint32_t smem_u32(const void* p) {
    uint32_t a;
    asm("{ .reg .u64 t; cvta.to.shared.u64 t, %1; cvt.u32.u64 %0, t; }"
        : "=r"(a) : "l"(p));
    return a;
}
__device__ __forceinline__ void ldm4(uint32_t* r, uint32_t addr) {
    asm volatile("ldmatrix.sync.aligned.m8n8.x4.shared.b16 {%0,%1,%2,%3}, [%4];"
                 : "=r"(r[0]), "=r"(r[1]), "=r"(r[2]), "=r"(r[3]) : "r"(addr));
}
__device__ __forceinline__ void mma16816(float* d, const uint32_t* a,
                                         uint32_t b0, uint32_t b1) {
    asm volatile(
        "mma.sync.aligned.m16n8k16.row.col.f32.f16.f16.f32 "
        "{%0,%1,%2,%3}, {%4,%5,%6,%7}, {%8,%9}, {%0,%1,%2,%3};"
        : "+f"(d[0]), "+f"(d[1]), "+f"(d[2]), "+f"(d[3])
        : "r"(a[0]), "r"(a[1]), "r"(a[2]), "r"(a[3]), "r"(b0), "r"(b1));
}

// ---------------------------------------------------------------------------
// prep: weight transpose (fp32 [K,C] -> fp16 [C,K]) fused with degi zeroing
// ---------------------------------------------------------------------------
__global__ void k_wt_zero(const float* __restrict__ W1, const float* __restrict__ W2,
                          const float* __restrict__ W3, __half* __restrict__ T1,
                          __half* __restrict__ T2, __half* __restrict__ T3,
                          int* __restrict__ degi, int n)
{
    int i = blockIdx.x * blockDim.x + threadIdx.x;
    if (i < n) degi[i] = 0;
    if (i < 16384) {
        int c = i >> 7, k = i & 127;
        T1[i] = __float2half(W1[k * 128 + c]);
    } else if (i < 32768) {
        int j = i - 16384, c = j >> 7, k = j & 127;
        T2[j] = __float2half(W2[k * 128 + c]);
    } else if (i < 40960) {
        int j = i - 32768, c = j >> 7, k = j & 127;
        T3[j] = __float2half(W3[k * 64 + c]);
    }
}
__global__ void k_count(const int* __restrict__ dst, int* degi, int e) {
    int i = blockIdx.x * blockDim.x + threadIdx.x;
    if (i < e) atomicAdd(&degi[dst[i]], 1);
}
__global__ void k_bsum(const int* __restrict__ degi, int* bsum, int n) {
    __shared__ int s[SCB];
    int i = blockIdx.x * SCB + threadIdx.x;
    s[threadIdx.x] = (i < n) ? degi[i] : 0;
    __syncthreads();
    for (int off = SCB / 2; off > 0; off >>= 1) {
        if (threadIdx.x < off) s[threadIdx.x] += s[threadIdx.x + off];
        __syncthreads();
    }
    if (threadIdx.x == 0) bsum[blockIdx.x] = s[0];
}
__global__ void k_scan_mid(int* bsum) {
    __shared__ int s[SCB];
    int t = threadIdx.x;
    s[t] = (t < NSC) ? bsum[t] : 0;
    __syncthreads();
    for (int off = 1; off < SCB; off *= 2) {
        int v = (t >= off) ? s[t - off] : 0;
        __syncthreads();
        s[t] += v;
        __syncthreads();
    }
    if (t < NSC) bsum[t] = (t == 0) ? 0 : s[t - 1];
}
__global__ void k_scan_emit(const int* __restrict__ degi, const int* __restrict__ bsum,
                            int* start, int* cursor, float* dis, float* dinv, int n)
{
    __shared__ int s[SCB];
    int i = blockIdx.x * SCB + threadIdx.x;
    int t = threadIdx.x;
    int d = (i < n) ? degi[i] : 0;
    s[t] = d;
    __syncthreads();
    for (int off = 1; off < SCB; off *= 2) {
        int v = (t >= off) ? s[t - off] : 0;
        __syncthreads();
        s[t] += v;
        __syncthreads();
    }
    if (i < n) {
        int run = bsum[blockIdx.x] + s[t] - d;
        start[i]  = run;
        cursor[i] = run;
        float df = (float)(d + 1);
        dis[i]  = rsqrtf(df);
        dinv[i] = 1.0f / df;
        if (i == n - 1) start[n] = run + d;
    }
}
__global__ void k_fill(const int* __restrict__ src, const int* __restrict__ dst,
                       const float* __restrict__ dis, int* cursor, int2* adj, int e)
{
    int i = blockIdx.x * blockDim.x + threadIdx.x;
    if (i >= e) return;
    int s = src[i], d = dst[i];
    int pos = atomicAdd(&cursor[d], 1);
    adj[pos] = make_int2(s, __float_as_int(dis[s] * dis[d]));
}

// ---------------------------------------------------------------------------
// HMMA GEMM: H[128rows, C] = X @ W ; writes H fp16 only.
// TIN = float (layer 1, converts) or __half (layers 2/3, direct copy).
// ---------------------------------------------------------------------------
template <int C, typename TIN>
__global__ void __launch_bounds__(256, 2) k_gemm_mma(
    const TIN* __restrict__ X, const __half* __restrict__ WT,
    __half* __restrict__ H, int nrows)
{
    constexpr int NCH = C / 8;
    constexpr int STR = 136;

    extern __shared__ __align__(16) __half smem[];
    __half* Xs = smem;
    __half* Ws = smem + 128 * STR;

    const int tid = threadIdx.x;
    const int l   = tid & 31;
    const int w   = tid >> 5;
    const int m0  = blockIdx.x * 128;

    if (sizeof(TIN) == 4) {   // fp32 input -> convert
        #pragma unroll
        for (int it = 0; it < 16; it++) {
            int idx = tid + it * 256;
            int row = idx >> 5;
            int q   = idx & 31;
            float4 v = make_float4(0.f, 0.f, 0.f, 0.f);
            if (m0 + row < nrows)
                v = *(const float4*)&((const float*)X)[(size_t)(m0 + row) * 128 + q * 4];
            __half2 h0 = __floats2half2_rn(v.x, v.y);
            __half2 h1 = __floats2half2_rn(v.z, v.w);
            uint2 pk = make_uint2(*(uint32_t*)&h0, *(uint32_t*)&h1);
            *(uint2*)&Xs[row * STR + q * 4] = pk;
        }
    } else {                  // fp16 input -> straight copy
        #pragma unroll
        for (int it = 0; it < 8; it++) {
            int idx = tid + it * 256;
            int row = idx >> 4;
            int q   = idx & 15;
            uint4 v = make_uint4(0, 0, 0, 0);
            if (m0 + row < nrows)
                v = *(const uint4*)&((const __half*)X)[(size_t)(m0 + row) * 128 + q * 8];
            *(uint4*)&Xs[row * STR + q * 8] = v;
        }
    }
    #pragma unroll
    for (int it = 0; it < C / 16; it++) {
        int idx = tid + it * 256;
        int n = idx >> 4;
        int q = idx & 15;
        uint4 v = *(const uint4*)&WT[n * 128 + q * 8];
        *(uint4*)&Ws[n * STR + q * 8] = v;
    }
    __syncthreads();

    float acc[NCH][4];
    #pragma unroll
    for (int c = 0; c < NCH; c++)
        #pragma unroll
        for (int j = 0; j < 4; j++) acc[c][j] = 0.f;

    const uint32_t sX = smem_u32(Xs);
    const uint32_t sW = smem_u32(Ws);
    const int lr = l & 15, lh = l >> 4;
    const uint32_t xbase = sX + (uint32_t)(((w * 16 + lr) * STR + lh * 8) * 2);
    const uint32_t wbase = sW + (uint32_t)((lr * STR + lh * 8) * 2);

    #pragma unroll
    for (int k = 0; k < 8; k++) {
        uint32_t a[4];
        ldm4(a, xbase + k * 32);
        #pragma unroll
        for (int c = 0; c < NCH / 2; c++) {
            uint32_t b[4];
            ldm4(b, wbase + c * (16 * STR * 2) + k * 32);
            mma16816(acc[2 * c],     a, b[0], b[2]);
            mma16816(acc[2 * c + 1], a, b[1], b[3]);
        }
    }

    int r0 = m0 + w * 16 + (l >> 2);
    int r1 = r0 + 8;
    int cb = (l & 3) * 2;
    bool ok0 = r0 < nrows, ok1 = r1 < nrows;
    #pragma unroll
    for (int c = 0; c < NCH; c++) {
        int col = c * 8 + cb;
        if (ok0) {
            __half2 h = __floats2half2_rn(acc[c][0], acc[c][1]);
            *(__half2*)&H[(size_t)r0 * C + col] = h;
        }
        if (ok1) {
            __half2 h = __floats2half2_rn(acc[c][2], acc[c][3]);
            *(__half2*)&H[(size_t)r1 * C + col] = h;
        }
    }
}

// ---------------------------------------------------------------------------
// CSR gather, warp per node. Computes out = act( dinv*H[node] + bias + sum ).
// TOUT = __half (layers 1/2, RELU) or float (layer 3, no relu).
// ---------------------------------------------------------------------------
template <int C, bool RELU, typename TOUT>
__global__ void __launch_bounds__(256) k_gather(
    const int* __restrict__ start, const int2* __restrict__ adj,
    const __half* __restrict__ H, const float* __restrict__ bias,
    const float* __restrict__ dinv, TOUT* __restrict__ OUT, int n)
{
    int node = (blockIdx.x * blockDim.x + threadIdx.x) >> 5;
    int lane = threadIdx.x & 31;
    if (node >= n) return;

    int s0 = start[node], s1 = start[node + 1];
    float di = dinv[node];

    if (C == 128) {
        float4 acc;
        {
            uint2 hs = *(const uint2*)&H[(size_t)node * 128 + lane * 4];
            float2 f0 = __half22float2(*(const __half2*)&hs.x);
            float2 f1 = __half22float2(*(const __half2*)&hs.y);
            float4 bv = *(const float4*)&bias[lane * 4];
            acc.x = fmaf(f0.x, di, bv.x);
            acc.y = fmaf(f0.y, di, bv.y);
            acc.z = fmaf(f1.x, di, bv.z);
            acc.w = fmaf(f1.y, di, bv.w);
        }
        int i = s0;
        for (; i + 3 < s1; i += 4) {
            int2 e0 = adj[i], e1 = adj[i + 1], e2 = adj[i + 2], e3 = adj[i + 3];
            uint2 h0 = *(const uint2*)&H[(size_t)e0.x * 128 + lane * 4];
            uint2 h1 = *(const uint2*)&H[(size_t)e1.x * 128 + lane * 4];
            uint2 h2 = *(const uint2*)&H[(size_t)e2.x * 128 + lane * 4];
            uint2 h3 = *(const uint2*)&H[(size_t)e3.x * 128 + lane * 4];
            float c0 = __int_as_float(e0.y), c1 = __int_as_float(e1.y);
            float c2 = __int_as_float(e2.y), c3 = __int_as_float(e3.y);
            float2 a0 = __half22float2(*(const __half2*)&h0.x);
            float2 b0 = __half22float2(*(const __half2*)&h0.y);
            float2 a1 = __half22float2(*(const __half2*)&h1.x);
            float2 b1 = __half22float2(*(const __half2*)&h1.y);
            float2 a2 = __half22float2(*(const __half2*)&h2.x);
            float2 b2 = __half22float2(*(const __half2*)&h2.y);
            float2 a3 = __half22float2(*(const __half2*)&h3.x);
            float2 b3 = __half22float2(*(const __half2*)&h3.y);
            acc.x = fmaf(a0.x, c0, fmaf(a1.x, c1, fmaf(a2.x, c2, fmaf(a3.x, c3, acc.x))));
            acc.y = fmaf(a0.y, c0, fmaf(a1.y, c1, fmaf(a2.y, c2, fmaf(a3.y, c3, acc.y))));
            acc.z = fmaf(b0.x, c0, fmaf(b1.x, c1, fmaf(b2.x, c2, fmaf(b3.x, c3, acc.z))));
            acc.w = fmaf(b0.y, c0, fmaf(b1.y, c1, fmaf(b2.y, c2, fmaf(b3.y, c3, acc.w))));
        }
        for (; i < s1; i++) {
            int2 e0 = adj[i];
            uint2 h0 = *(const uint2*)&H[(size_t)e0.x * 128 + lane * 4];
            float c0 = __int_as_float(e0.y);
            float2 a0 = __half22float2(*(const __half2*)&h0.x);
            float2 b0 = __half22float2(*(const __half2*)&h0.y);
            acc.x = fmaf(a0.x, c0, acc.x);
            acc.y = fmaf(a0.y, c0, acc.y);
            acc.z = fmaf(b0.x, c0, acc.z);
            acc.w = fmaf(b0.y, c0, acc.w);
        }
        if (RELU) {
            acc.x = fmaxf(acc.x, 0.f); acc.y = fmaxf(acc.y, 0.f);
            acc.z = fmaxf(acc.z, 0.f); acc.w = fmaxf(acc.w, 0.f);
        }
        if (sizeof(TOUT) == 2) {
            __half2 o0 = __floats2half2_rn(acc.x, acc.y);
            __half2 o1 = __floats2half2_rn(acc.z, acc.w);
            uint2 pk = make_uint2(*(uint32_t*)&o0, *(uint32_t*)&o1);
            *(uint2*)&((__half*)OUT)[(size_t)node * 128 + lane * 4] = pk;
        } else {
            *(float4*)&((float*)OUT)[(size_t)node * 128 + lane * 4] = acc;
        }
    } else {  // C == 64
        float2 acc;
        {
            uint32_t hs = *(const uint32_t*)&H[(size_t)node * 64 + lane * 2];
            float2 f0 = __half22float2(*(const __half2*)&hs);
            float2 bv = *(const float2*)&bias[lane * 2];
            acc.x = fmaf(f0.x, di, bv.x);
            acc.y = fmaf(f0.y, di, bv.y);
        }
        int i = s0;
        for (; i + 3 < s1; i += 4) {
            int2 e0 = adj[i], e1 = adj[i + 1], e2 = adj[i + 2], e3 = adj[i + 3];
            uint32_t h0 = *(const uint32_t*)&H[(size_t)e0.x * 64 + lane * 2];
            uint32_t h1 = *(const uint32_t*)&H[(size_t)e1.x * 64 + lane * 2];
            uint32_t h2 = *(const uint32_t*)&H[(size_t)e2.x * 64 + lane * 2];
            uint32_t h3 = *(const uint32_t*)&H[(size_t)e3.x * 64 + lane * 2];
            float c0 = __int_as_float(e0.y), c1 = __int_as_float(e1.y);
            float c2 = __int_as_float(e2.y), c3 = __int_as_float(e3.y);
            float2 a0 = __half22float2(*(const __half2*)&h0);
            float2 a1 = __half22float2(*(const __half2*)&h1);
            float2 a2 = __half22float2(*(const __half2*)&h2);
            float2 a3 = __half22float2(*(const __half2*)&h3);
            acc.x = fmaf(a0.x, c0, fmaf(a1.x, c1, fmaf(a2.x, c2, fmaf(a3.x, c3, acc.x))));
            acc.y = fmaf(a0.y, c0, fmaf(a1.y, c1, fmaf(a2.y, c2, fmaf(a3.y, c3, acc.y))));
        }
        for (; i < s1; i++) {
            int2 e0 = adj[i];
            uint32_t h0 = *(const uint32_t*)&H[(size_t)e0.x * 64 + lane * 2];
            float c0 = __int_as_float(e0.y);
            float2 a0 = __half22float2(*(const __half2*)&h0);
            acc.x = fmaf(a0.x, c0, acc.x);
            acc.y = fmaf(a0.y, c0, acc.y);
        }
        if (RELU) { acc.x = fmaxf(acc.x, 0.f); acc.y = fmaxf(acc.y, 0.f); }
        if (sizeof(TOUT) == 2) {
            __half2 o0 = __floats2half2_rn(acc.x, acc.y);
            *(uint32_t*)&((__half*)OUT)[(size_t)node * 64 + lane * 2] = *(uint32_t*)&o0;
        } else {
            *(float2*)&((float*)OUT)[(size_t)node * 64 + lane * 2] = acc;
        }
    }
}

// ---------------------------------------------------------------------------
extern "C" void kernel_launch(void* const* d_in, const int* in_sizes, int n_in,
                              void* d_out, int out_size)
{
    const float* x  = (const float*)d_in[0];
    const int*   ei = (const int*)d_in[1];
    const float* W1 = (const float*)d_in[2];
    const float* b1 = (const float*)d_in[3];
    const float* W2 = (const float*)d_in[4];
    const float* b2 = (const float*)d_in[5];
    const float* W3 = (const float*)d_in[6];
    const float* b3 = (const float*)d_in[7];
    float* out = (float*)d_out;

    const int E = in_sizes[1] / 2;
    const int N = in_sizes[0] / 128;
    const int* src = ei;
    const int* dst = ei + E;

    __half *ph, *pa1, *pa2, *pwt1, *pwt2, *pwt3;
    float *pdis, *pdinv;
    int *pdegi, *pbsum, *pstart, *pcursor;
    int2 *padj;
    cudaGetSymbolAddress((void**)&ph,      g_h);
    cudaGetSymbolAddress((void**)&pa1,     g_agg1);
    cudaGetSymbolAddress((void**)&pa2,     g_agg2);
    cudaGetSymbolAddress((void**)&pdis,    g_dis);
    cudaGetSymbolAddress((void**)&pdinv,   g_dinv);
    cudaGetSymbolAddress((void**)&pdegi,   g_degi);
    cudaGetSymbolAddress((void**)&pbsum,   g_bsum);
    cudaGetSymbolAddress((void**)&pstart,  g_start);
    cudaGetSymbolAddress((void**)&pcursor, g_cursor);
    cudaGetSymbolAddress((void**)&padj,    g_adj);
    cudaGetSymbolAddress((void**)&pwt1,    g_wt1);
    cudaGetSymbolAddress((void**)&pwt2,    g_wt2);
    cudaGetSymbolAddress((void**)&pwt3,    g_wt3);

    const int SM128 = (128 + 128) * 136 * 2;
    const int SM64  = (128 + 64) * 136 * 2;
    cudaFuncSetAttribute(k_gemm_mma<128, float>,  cudaFuncAttributeMaxDynamicSharedMemorySize, SM128);
    cudaFuncSetAttribute(k_gemm_mma<128, __half>, cudaFuncAttributeMaxDynamicSharedMemorySize, SM128);
    cudaFuncSetAttribute(k_gemm_mma<64, __half>,  cudaFuncAttributeMaxDynamicSharedMemorySize, SM64);

    // prep + CSR build
    k_wt_zero<<<(N + 255) / 256, 256>>>(W1, W2, W3, pwt1, pwt2, pwt3, pdegi, N);
    k_count<<<(E + 255) / 256, 256>>>(dst, pdegi, E);
    k_bsum<<<NSC, SCB>>>(pdegi, pbsum, N);
    k_scan_mid<<<1, SCB>>>(pbsum);
    k_scan_emit<<<NSC, SCB>>>(pdegi, pbsum, pstart, pcursor, pdis, pdinv, N);
    k_fill<<<(E + 255) / 256, 256>>>(src, dst, pdis, pcursor, padj, E);

    const int gb = (N + 127) / 128;
    const int gatb = (N * 32 + 255) / 256;

    k_gemm_mma<128, float><<<gb, 256, SM128>>>(x, pwt1, ph, N);
    k_gather<128, true, __half><<<gatb, 256>>>(pstart, padj, ph, b1, pdinv, pa1, N);

    k_gemm_mma<128, __half><<<gb, 256, SM128>>>(pa1, pwt2, ph, N);
    k_gather<128, true, __half><<<gatb, 256>>>(pstart, padj, ph, b2, pdinv, pa2, N);

    k_gemm_mma<64, __half><<<gb, 256, SM64>>>(pa2, pwt3, ph, N);
    k_gather<64, false, float><<<gatb, 256>>>(pstart, padj, ph, b3, pdinv, out, N);
}